// round 2
// baseline (speedup 1.0000x reference)
#include <cuda_runtime.h>
#include <cuda_bf16.h>

// out[b,e] = sparsity[b,e] * sum_h hs[b,h] * ws[e,h]
//   hs[b,h] = sum_m hidden[b,m,h]   (4 MB read)
//   ws[e,h] = sum_n weight[e,h,n]   (32 MB read)
// A=1, B=32, M=32, H=1024, E=8, N=1024.  Single fused kernel.

#define Bn 32
#define Mn 32
#define Hn 1024
#define En 8
#define Nn 1024
#define NBLK ((En * Hn) / 8)   // 1024 blocks, 8 warps each -> one (e,h) row per warp

__device__ float g_hs[Bn * Hn];       // hs[b*H + h]
__device__ int   g_flag = 0;          // hidden-done counter (0..32)
__device__ int   g_done = 0;          // block-done counter for flag reset

__global__ void __launch_bounds__(256, 8) fused_kernel(
    const float* __restrict__ hidden,
    const float* __restrict__ sparsity,
    const float* __restrict__ weight,
    float* __restrict__ out)
{
    const int tid  = threadIdx.x;
    const int lane = tid & 31;
    const int wid  = tid >> 5;
    const int bid  = blockIdx.x;

    // ---- Phase A (blocks 0..31): hidden reduction for b = bid, zero out slice ----
    if (bid < Bn) {
        const int b = bid;
        // each thread owns one float4 column (4 h values), sums over m
        const float4* base = reinterpret_cast<const float4*>(hidden + (size_t)b * Mn * Hn);
        float4 acc = make_float4(0.f, 0.f, 0.f, 0.f);
        #pragma unroll
        for (int m = 0; m < Mn; m++) {
            float4 v = base[m * (Hn / 4) + tid];
            acc.x += v.x; acc.y += v.y; acc.z += v.z; acc.w += v.w;
        }
        reinterpret_cast<float4*>(g_hs + b * Hn)[tid] = acc;
        if (tid < En) out[b * En + tid] = 0.f;
        __syncthreads();
        if (tid == 0) {
            __threadfence();
            atomicAdd(&g_flag, 1);
        }
    }

    // ---- Phase B (all blocks): weight row sums. row r = bid*8 + wid ----
    // All 8 rows of a block share e = bid >> 7 (since 8 divides 1024).
    const int r = bid * 8 + wid;          // e*1024 + h
    const int e = bid >> 7;
    const float4* row = reinterpret_cast<const float4*>(weight + (size_t)r * Nn);
    float s = 0.f;
    #pragma unroll
    for (int k = 0; k < Nn / 4 / 32; k++) {   // 8 float4 per lane
        float4 v = row[lane + k * 32];
        s += (v.x + v.y) + (v.z + v.w);
    }
    #pragma unroll
    for (int off = 16; off > 0; off >>= 1)
        s += __shfl_xor_sync(0xffffffffu, s, off);

    __shared__ float ws_sm[8];   // wsum for this block's 8 h values
    if (lane == 0) ws_sm[wid] = s;

    // ---- Wait for hidden sums (blocks 0..31 never wait on anyone -> no deadlock) ----
    if (tid == 0) {
        while (atomicAdd(&g_flag, 0) < Bn) __nanosleep(64);
    }
    __syncthreads();

    // ---- Phase C: warp 0 accumulates partial[b] = sum_j ws_sm[j]*hs[b, h_j] ----
    if (wid == 0 && lane < Bn) {
        const int b = lane;
        const int h0 = (bid * 8) & (Hn - 1);    // first h of this block
        float partial = 0.f;
        #pragma unroll
        for (int j = 0; j < 8; j++)
            partial += ws_sm[j] * __ldcg(&g_hs[b * Hn + h0 + j]);
        const int idx = b * En + e;
        atomicAdd(&out[idx], partial * __ldcg(&sparsity[idx]));
    }

    // ---- Reset flag for next graph replay (last block to finish does it) ----
    __syncthreads();
    if (tid == 0) {
        __threadfence();
        int t = atomicAdd(&g_done, 1);
        if (t == NBLK - 1) {
            g_flag = 0;
            g_done = 0;
            __threadfence();
        }
    }
}

extern "C" void kernel_launch(void* const* d_in, const int* in_sizes, int n_in,
                              void* d_out, int out_size)
{
    const float* hidden   = (const float*)d_in[0];
    const float* sparsity = (const float*)d_in[1];
    const float* weight   = (const float*)d_in[2];
    float* out = (float*)d_out;

    fused_kernel<<<NBLK, 256>>>(hidden, sparsity, weight, out);
}

// round 3
// speedup vs baseline: 1.0917x; 1.0917x over previous
#include <cuda_runtime.h>
#include <cuda_bf16.h>

// out[b,e] = sparsity[b,e] * sum_h hs[b,h] * ws[e,h]
//   hs[b,h] = sum_m hidden[b,m,h]   (4 MB read)
//   ws[e,h] = sum_n weight[e,h,n]   (32 MB read)
// A=1, B=32, M=32, H=1024, E=8, N=1024.
// Kernel 1: hidden sums (wide grid) + zero out.
// Kernel 2: weight row sums + fused dot epilogue (atomics). Graph edge = sync.

#define Bn 32
#define Mn 32
#define Hn 1024
#define En 8
#define Nn 1024

__device__ float g_hs[Bn * Hn];   // hs[b*H + h]

// 256 blocks x 128 threads. Block (b, chunk): b = bid>>3, h0 = (bid&7)*128.
// Thread t owns h = h0 + t; sums hidden[b, m, h] over m (32 independent loads).
__global__ void __launch_bounds__(128) hidden_kernel(
    const float* __restrict__ hidden,
    float* __restrict__ out)
{
    const int bid = blockIdx.x;
    const int b   = bid >> 3;
    const int h   = ((bid & 7) << 7) + threadIdx.x;
    const float* base = hidden + (size_t)b * Mn * Hn + h;

    float s = 0.f;
    #pragma unroll
    for (int m = 0; m < Mn; m++)
        s += base[m * Hn];
    g_hs[b * Hn + h] = s;

    // zero the 256-float output (blocks 0 and 1)
    if (bid < 2) out[bid * 128 + threadIdx.x] = 0.f;
}

// 1024 blocks x 256 threads. Warp w of block bid owns weight row r = bid*8 + w
// (r = e*1024 + h; all 8 rows of a block share e = bid>>7 since 8 | 1024).
// After row sums, warp 0 accumulates the dot contribution for all 32 b.
__global__ void __launch_bounds__(256) weight_kernel(
    const float* __restrict__ sparsity,
    const float* __restrict__ weight,
    float* __restrict__ out)
{
    const int tid  = threadIdx.x;
    const int lane = tid & 31;
    const int wid  = tid >> 5;
    const int bid  = blockIdx.x;

    const int r = bid * 8 + wid;          // e*1024 + h
    const int e = bid >> 7;

    const float4* row = reinterpret_cast<const float4*>(weight + (size_t)r * Nn);
    float s = 0.f;
    #pragma unroll
    for (int k = 0; k < Nn / 4 / 32; k++) {   // 8 float4 per lane, fully coalesced
        float4 v = row[lane + k * 32];
        s += (v.x + v.y) + (v.z + v.w);
    }
    #pragma unroll
    for (int off = 16; off > 0; off >>= 1)
        s += __shfl_xor_sync(0xffffffffu, s, off);

    __shared__ float ws_sm[8];
    if (lane == 0) ws_sm[wid] = s;
    __syncthreads();

    // Epilogue: lane b of warp 0 accumulates over this block's 8 h values.
    if (wid == 0) {
        const int b  = lane;                  // 32 lanes = 32 b values
        const int h0 = (bid * 8) & (Hn - 1);
        const float* hs = g_hs + b * Hn + h0; // L2-resident (128 KB total)
        float partial = 0.f;
        #pragma unroll
        for (int j = 0; j < 8; j++)
            partial += ws_sm[j] * hs[j];
        const int idx = b * En + e;
        atomicAdd(&out[idx], partial * sparsity[idx]);
    }
}

extern "C" void kernel_launch(void* const* d_in, const int* in_sizes, int n_in,
                              void* d_out, int out_size)
{
    const float* hidden   = (const float*)d_in[0];
    const float* sparsity = (const float*)d_in[1];
    const float* weight   = (const float*)d_in[2];
    float* out = (float*)d_out;

    hidden_kernel<<<256, 128>>>(hidden, out);
    weight_kernel<<<(En * Hn) / 8, 256>>>(sparsity, weight, out);
}

// round 4
// speedup vs baseline: 1.1083x; 1.0152x over previous
#include <cuda_runtime.h>
#include <cuda_bf16.h>

// out[b,e] = sparsity[b,e] * sum_h hs[b,h] * ws[e,h]
//   hs[b,h] = sum_m hidden[b,m,h]   (4 MB read)
//   ws[e,h] = sum_n weight[e,h,n]   (32 MB read)
// A=1, B=32, M=32, H=1024, E=8, N=1024.
//
// Kernel 1: hidden sums -> TRANSPOSED scratch g_hsT[h*32+b]; zero out.
// Kernel 2: weight row sums + coalesced fused dot epilogue (1 RED-warp/block).

#define Bn 32
#define Mn 32
#define Hn 1024
#define En 8
#define Nn 1024

__device__ float g_hsT[Hn * Bn];   // hsT[h*32 + b]  (128 KB, L2-resident)

// 256 blocks x 128 threads. b = bid>>3, h = (bid&7)*128 + tid.
// Reads coalesced over h; transposed writes are only 32K stores total.
__global__ void __launch_bounds__(128) hidden_kernel(
    const float* __restrict__ hidden,
    float* __restrict__ out)
{
    const int bid = blockIdx.x;
    const int b   = bid >> 3;
    const int h   = ((bid & 7) << 7) + threadIdx.x;
    const float* base = hidden + (size_t)b * Mn * Hn + h;

    float s = 0.f;
    #pragma unroll
    for (int m = 0; m < Mn; m++)
        s += base[m * Hn];
    g_hsT[h * Bn + b] = s;

    if (bid < 2) out[bid * 128 + threadIdx.x] = 0.f;   // zero 256-float output
}

// 1024 blocks x 256 threads. Warp w owns weight row r = bid*8 + w = e*1024 + h
// (all 8 rows of a block share e = bid>>7). Streaming identical to R1's 6 us
// reduce kernel; epilogue adds only 8 coalesced L2 loads + smem + 1 RED-warp.
__global__ void __launch_bounds__(256) weight_kernel(
    const float* __restrict__ sparsity,
    const float* __restrict__ weight,
    float* __restrict__ out)
{
    const int tid  = threadIdx.x;
    const int lane = tid & 31;
    const int wid  = tid >> 5;
    const int bid  = blockIdx.x;

    const int r = bid * 8 + wid;          // e*1024 + h
    const int e = bid >> 7;
    const int h = r & (Hn - 1);

    const float4* row = reinterpret_cast<const float4*>(weight + (size_t)r * Nn);
    float s = 0.f;
    #pragma unroll
    for (int k = 0; k < Nn / 4 / 32; k++) {   // 8 float4 per lane, coalesced
        float4 v = row[lane + k * 32];
        s += (v.x + v.y) + (v.z + v.w);
    }
    #pragma unroll
    for (int off = 16; off > 0; off >>= 1)
        s += __shfl_xor_sync(0xffffffffu, s, off);
    // every lane of warp w now holds ws[e, h]

    // Coalesced epilogue: lane b loads hsT[h*32 + b] (single 128B line per warp)
    const float contrib = s * g_hsT[h * Bn + lane];

    __shared__ float psum[8][32];
    psum[wid][lane] = contrib;
    __syncthreads();

    if (wid == 0) {
        float p = psum[0][lane];
        #pragma unroll
        for (int j = 1; j < 8; j++)
            p += psum[j][lane];
        const int idx = lane * En + e;     // b = lane
        atomicAdd(&out[idx], p * sparsity[idx]);   // result unused -> REDG
    }
}

extern "C" void kernel_launch(void* const* d_in, const int* in_sizes, int n_in,
                              void* d_out, int out_size)
{
    const float* hidden   = (const float*)d_in[0];
    const float* sparsity = (const float*)d_in[1];
    const float* weight   = (const float*)d_in[2];
    float* out = (float*)d_out;

    hidden_kernel<<<256, 128>>>(hidden, out);
    weight_kernel<<<(En * Hn) / 8, 256>>>(sparsity, weight, out);
}

// round 5
// speedup vs baseline: 1.9552x; 1.7642x over previous
#include <cuda_runtime.h>

// out[b,e] = sparsity[b,e] * sum_h hs[b,h] * ws[e,h]
//   ws[e,h] = sum_n weight[e,h,n]   (32 MB read)  -> kernel 1 (pure streaming)
//   hs[b,h] = sum_m hidden[b,m,h]   (4 MB read)   -> kernel 2, dot fused in
// A=1, B=32, M=32, H=1024, E=8, N=1024.

#define Bn 32
#define Mn 32
#define Hn 1024
#define En 8
#define Nn 1024

__device__ float g_wsT[Hn * En];   // wsT[h*8 + e]  (32 KB, L2-resident)

// ---- Kernel 1: pure weight row-sum streaming. 512 blocks x 256 threads.
// Warp w owns rows r0 = bid*16 + 2w and r0+1 (16 | 1024 => whole block same e).
// Two rows interleaved -> 16 outstanding LDG.128 per warp. NO sync, NO atomics.
__global__ void __launch_bounds__(256) weight_kernel(
    const float* __restrict__ weight,
    float* __restrict__ out)
{
    const int tid  = threadIdx.x;
    const int lane = tid & 31;
    const int wid  = tid >> 5;
    const int r0   = blockIdx.x * 16 + wid * 2;

    const float4* rowA = reinterpret_cast<const float4*>(weight + (size_t)r0 * Nn);
    const float4* rowB = reinterpret_cast<const float4*>(weight + (size_t)(r0 + 1) * Nn);

    float s0 = 0.f, s1 = 0.f;
    #pragma unroll
    for (int k = 0; k < Nn / 4 / 32; k++) {   // 8 float4 per lane per row
        float4 a = rowA[lane + k * 32];
        float4 b = rowB[lane + k * 32];
        s0 += (a.x + a.y) + (a.z + a.w);
        s1 += (b.x + b.y) + (b.z + b.w);
    }
    #pragma unroll
    for (int off = 16; off > 0; off >>= 1) {
        s0 += __shfl_xor_sync(0xffffffffu, s0, off);
        s1 += __shfl_xor_sync(0xffffffffu, s1, off);
    }
    if (lane == 0) {
        const int e  = r0 >> 10;
        const int h0 = r0 & (Hn - 1);
        g_wsT[h0 * En + e]       = s0;
        g_wsT[(h0 + 1) * En + e] = s1;
    }
    if (blockIdx.x == 0) out[tid] = 0.f;   // zero all 256 outputs
}

// ---- Kernel 2: hidden reduction + fused dot. 256 blocks x 128 threads.
// Block (b, chunk): b = bid>>3, h = (bid&7)*128 + tid. Thread computes
// hs = sum_m hidden[b,m,h], multiplies by wsT[h*8+e] (coalesced float4 x2),
// block-reduces 8 partials, 8 atomics into out.
__global__ void __launch_bounds__(128) hidden_dot_kernel(
    const float* __restrict__ hidden,
    const float* __restrict__ sparsity,
    float* __restrict__ out)
{
    const int bid  = blockIdx.x;
    const int tid  = threadIdx.x;
    const int lane = tid & 31;
    const int wid  = tid >> 5;
    const int b    = bid >> 3;
    const int h    = ((bid & 7) << 7) + tid;

    const float* base = hidden + (size_t)b * Mn * Hn + h;
    float s = 0.f;
    #pragma unroll
    for (int m = 0; m < Mn; m++)     // 32 independent strided-coalesced loads
        s += base[m * Hn];

    // ws for this h: 8 contiguous floats (warp reads 1 KB contiguous)
    const float4* wt = reinterpret_cast<const float4*>(g_wsT + h * En);
    const float4 w0 = wt[0], w1 = wt[1];

    float p[8] = { s * w0.x, s * w0.y, s * w0.z, s * w0.w,
                   s * w1.x, s * w1.y, s * w1.z, s * w1.w };

    #pragma unroll
    for (int off = 16; off > 0; off >>= 1)
        #pragma unroll
        for (int e = 0; e < 8; e++)
            p[e] += __shfl_xor_sync(0xffffffffu, p[e], off);

    __shared__ float sm[4][8];
    if (lane == 0)
        #pragma unroll
        for (int e = 0; e < 8; e++) sm[wid][e] = p[e];
    __syncthreads();

    if (tid < En) {
        const float v = sm[0][tid] + sm[1][tid] + sm[2][tid] + sm[3][tid];
        const int idx = b * En + tid;
        atomicAdd(&out[idx], v * sparsity[idx]);   // 8 REDs per block
    }
}

extern "C" void kernel_launch(void* const* d_in, const int* in_sizes, int n_in,
                              void* d_out, int out_size)
{
    const float* hidden   = (const float*)d_in[0];
    const float* sparsity = (const float*)d_in[1];
    const float* weight   = (const float*)d_in[2];
    float* out = (float*)d_out;

    weight_kernel<<<(En * Hn) / 16, 256>>>(weight, out);        // 512 blocks
    hidden_dot_kernel<<<Bn * 8, 128>>>(hidden, sparsity, out);  // 256 blocks
}